// round 4
// baseline (speedup 1.0000x reference)
#include <cuda_runtime.h>

#define Nn 50000
#define Ee 800000
#define ET (Ee + Nn)
#define F 128
#define NB 16          // nodes per gemm block

// ---- scratch (device globals; no allocations) ----
__device__ float g_h   [Nn * F];
__device__ float g_buf [Nn * F];
__device__ float g_al_s[Nn * 8];
__device__ float g_al_d[Nn * 8];
__device__ int   g_cnt [Nn];
__device__ int   g_rp  [Nn + 1];
__device__ int   g_cur [Nn];
__device__ int   g_col [ET];       // src node per incoming edge, grouped by dst

__device__ __forceinline__ float lrelu(float v) { return v > 0.f ? v : 0.2f * v; }

// ================= CSR build (once per launch) =================
__global__ void csr_zero()
{
    int i = blockIdx.x * blockDim.x + threadIdx.x;
    if (i < Nn) g_cnt[i] = 0;
}

__global__ void csr_hist(const int* __restrict__ ei)
{
    int e = blockIdx.x * blockDim.x + threadIdx.x;
    if (e >= ET) return;
    int dst = (e < Ee) ? ei[Ee + e] : e - Ee;
    atomicAdd(&g_cnt[dst], 1);
}

__global__ void csr_scan()   // single block, 1024 threads
{
    __shared__ int sp[1024];
    int t = threadIdx.x;
    const int CH = (Nn + 1023) / 1024;
    int base = t * CH;
    int s = 0;
    for (int i = 0; i < CH; i++) { int idx = base + i; if (idx < Nn) s += g_cnt[idx]; }
    sp[t] = s;
    __syncthreads();
    for (int off = 1; off < 1024; off <<= 1) {
        int v = (t >= off) ? sp[t - off] : 0;
        __syncthreads();
        sp[t] += v;
        __syncthreads();
    }
    int run = (t == 0) ? 0 : sp[t - 1];
    for (int i = 0; i < CH; i++) {
        int idx = base + i;
        if (idx < Nn) { g_rp[idx] = run; g_cur[idx] = run; run += g_cnt[idx]; }
    }
    if (t == 1023) g_rp[Nn] = ET;
}

__global__ void csr_fill(const int* __restrict__ ei)
{
    int e = blockIdx.x * blockDim.x + threadIdx.x;
    if (e >= ET) return;
    int src, dst;
    if (e < Ee) { src = ei[e]; dst = ei[Ee + e]; }
    else        { src = dst = e - Ee; }
    int pos = atomicAdd(&g_cur[dst], 1);
    g_col[pos] = src;
}

// ================= GEMM + attention logits =================
__global__ void gemm_attn(const float* __restrict__ xg, int use_buf,
                          const float* __restrict__ W,
                          const float* __restrict__ asv,
                          const float* __restrict__ adv, int H)
{
    const float* xin = use_buf ? g_buf : xg;
    __shared__ __align__(16) float xs[F][20];   // [k][node_local], padded

    int tid = threadIdx.x;
    int cg  = tid & 31;
    int ng  = tid >> 5;
    int n0  = blockIdx.x * NB;

#pragma unroll
    for (int i = 0; i < NB; i++) xs[tid][i] = xin[(n0 + i) * F + tid];
    __syncthreads();

    float4 acc[4];
#pragma unroll
    for (int a = 0; a < 4; a++) acc[a] = make_float4(0.f, 0.f, 0.f, 0.f);

#pragma unroll 4
    for (int k = 0; k < F; k++) {
        float4 xv = *reinterpret_cast<const float4*>(&xs[k][ng * 4]);   // broadcast
        float4 wv = *reinterpret_cast<const float4*>(&W[k * F + cg * 4]);
        acc[0].x += xv.x * wv.x; acc[0].y += xv.x * wv.y; acc[0].z += xv.x * wv.z; acc[0].w += xv.x * wv.w;
        acc[1].x += xv.y * wv.x; acc[1].y += xv.y * wv.y; acc[1].z += xv.y * wv.z; acc[1].w += xv.y * wv.w;
        acc[2].x += xv.z * wv.x; acc[2].y += xv.z * wv.y; acc[2].z += xv.z * wv.z; acc[2].w += xv.z * wv.w;
        acc[3].x += xv.w * wv.x; acc[3].y += xv.w * wv.y; acc[3].z += xv.w * wv.z; acc[3].w += xv.w * wv.w;
    }

    float4 av = *reinterpret_cast<const float4*>(&asv[cg * 4]);
    float4 dv = *reinterpret_cast<const float4*>(&adv[cg * 4]);

#pragma unroll
    for (int a = 0; a < 4; a++) {
        int n = n0 + ng * 4 + a;
        *reinterpret_cast<float4*>(&g_h[n * F + cg * 4]) = acc[a];
        float ps = acc[a].x * av.x + acc[a].y * av.y + acc[a].z * av.z + acc[a].w * av.w;
        float pd = acc[a].x * dv.x + acc[a].y * dv.y + acc[a].z * dv.z + acc[a].w * dv.w;
        if (H == 8) {
            ps += __shfl_xor_sync(0xffffffffu, ps, 1);
            ps += __shfl_xor_sync(0xffffffffu, ps, 2);
            pd += __shfl_xor_sync(0xffffffffu, pd, 1);
            pd += __shfl_xor_sync(0xffffffffu, pd, 2);
            if ((cg & 3) == 0) {
                g_al_s[n * 8 + (cg >> 2)] = ps;
                g_al_d[n * 8 + (cg >> 2)] = pd;
            }
        } else {
#pragma unroll
            for (int o = 1; o < 32; o <<= 1) {
                ps += __shfl_xor_sync(0xffffffffu, ps, o);
                pd += __shfl_xor_sync(0xffffffffu, pd, o);
            }
            if (cg == 0) { g_al_s[n * 8] = ps; g_al_d[n * 8] = pd; }
        }
    }
}

// ================= fused per-node softmax-aggregate + LN (+ELU) =================
// one warp per dst node; batches of 4 edges; whole warp computes 4x8 exps at once
__global__ void node_agg(const float* __restrict__ b, const float* __restrict__ gg,
                         const float* __restrict__ be, float* __restrict__ out,
                         int do_elu, int H)
{
    int n = blockIdx.x * 8 + (threadIdx.x >> 5);
    if (n >= Nn) return;
    int lane  = threadIdx.x & 31;
    int hfeat = lane >> 2;                 // head owning this lane's 4 features

    int begin = g_rp[n], end = g_rp[n + 1];
    float4 acc = make_float4(0.f, 0.f, 0.f, 0.f);
    float  ssum = 0.f;

    if (H == 8) {
        float ald = g_al_d[n * 8 + (lane & 7)];
        int i = begin;
        // peel until 16B-aligned index
        for (; i < end && (i & 3); i++) {
            int s0 = g_col[i];
            float ex0 = 0.f;
            if (lane < 8) { ex0 = __expf(lrelu(g_al_s[s0 * 8 + lane] + ald)); ssum += ex0; }
            float e0 = __shfl_sync(0xffffffffu, ex0, hfeat);
            float4 h0 = *reinterpret_cast<const float4*>(&g_h[s0 * F + lane * 4]);
            acc.x += h0.x * e0; acc.y += h0.y * e0; acc.z += h0.z * e0; acc.w += h0.w * e0;
        }
        // main: 4 edges per iteration; lane = slot*8 + head
        for (; i + 4 <= end; i += 4) {
            int4 c4 = *reinterpret_cast<const int4*>(&g_col[i]);
            int slot = lane >> 3;
            int sj = (slot == 0) ? c4.x : (slot == 1) ? c4.y : (slot == 2) ? c4.z : c4.w;
            float ex = __expf(lrelu(__ldg(&g_al_s[sj * 8 + (lane & 7)]) + ald));
            ssum += ex;
            float e0 = __shfl_sync(0xffffffffu, ex, hfeat);
            float e1 = __shfl_sync(0xffffffffu, ex, 8  + hfeat);
            float e2 = __shfl_sync(0xffffffffu, ex, 16 + hfeat);
            float e3 = __shfl_sync(0xffffffffu, ex, 24 + hfeat);
            float4 h0 = *reinterpret_cast<const float4*>(&g_h[c4.x * F + lane * 4]);
            float4 h1 = *reinterpret_cast<const float4*>(&g_h[c4.y * F + lane * 4]);
            float4 h2 = *reinterpret_cast<const float4*>(&g_h[c4.z * F + lane * 4]);
            float4 h3 = *reinterpret_cast<const float4*>(&g_h[c4.w * F + lane * 4]);
            acc.x += h0.x * e0 + h1.x * e1 + h2.x * e2 + h3.x * e3;
            acc.y += h0.y * e0 + h1.y * e1 + h2.y * e2 + h3.y * e3;
            acc.z += h0.z * e0 + h1.z * e1 + h2.z * e2 + h3.z * e3;
            acc.w += h0.w * e0 + h1.w * e1 + h2.w * e2 + h3.w * e3;
        }
        // tail
        for (; i < end; i++) {
            int s0 = g_col[i];
            float ex0 = 0.f;
            if (lane < 8) { ex0 = __expf(lrelu(g_al_s[s0 * 8 + lane] + ald)); ssum += ex0; }
            float e0 = __shfl_sync(0xffffffffu, ex0, hfeat);
            float4 h0 = *reinterpret_cast<const float4*>(&g_h[s0 * F + lane * 4]);
            acc.x += h0.x * e0; acc.y += h0.y * e0; acc.z += h0.z * e0; acc.w += h0.w * e0;
        }
        // per-head totals: lanes {h, h+8, h+16, h+24} hold partials for head h
        ssum += __shfl_xor_sync(0xffffffffu, ssum, 8);
        ssum += __shfl_xor_sync(0xffffffffu, ssum, 16);
        ssum  = __shfl_sync(0xffffffffu, ssum, hfeat);
    } else {
        float ald = g_al_d[n * 8];
        int i = begin;
        for (; i < end && (i & 3); i++) {
            int s0 = g_col[i];
            float ex0 = 0.f;
            if (lane == 0) { ex0 = __expf(lrelu(g_al_s[s0 * 8] + ald)); ssum += ex0; }
            float e0 = __shfl_sync(0xffffffffu, ex0, 0);
            float4 h0 = *reinterpret_cast<const float4*>(&g_h[s0 * F + lane * 4]);
            acc.x += h0.x * e0; acc.y += h0.y * e0; acc.z += h0.z * e0; acc.w += h0.w * e0;
        }
        for (; i + 4 <= end; i += 4) {
            int4 c4 = *reinterpret_cast<const int4*>(&g_col[i]);
            float ex = 0.f;
            if (lane < 4) {
                int sj = (lane == 0) ? c4.x : (lane == 1) ? c4.y : (lane == 2) ? c4.z : c4.w;
                ex = __expf(lrelu(__ldg(&g_al_s[sj * 8]) + ald));
                ssum += ex;
            }
            float e0 = __shfl_sync(0xffffffffu, ex, 0);
            float e1 = __shfl_sync(0xffffffffu, ex, 1);
            float e2 = __shfl_sync(0xffffffffu, ex, 2);
            float e3 = __shfl_sync(0xffffffffu, ex, 3);
            float4 h0 = *reinterpret_cast<const float4*>(&g_h[c4.x * F + lane * 4]);
            float4 h1 = *reinterpret_cast<const float4*>(&g_h[c4.y * F + lane * 4]);
            float4 h2 = *reinterpret_cast<const float4*>(&g_h[c4.z * F + lane * 4]);
            float4 h3 = *reinterpret_cast<const float4*>(&g_h[c4.w * F + lane * 4]);
            acc.x += h0.x * e0 + h1.x * e1 + h2.x * e2 + h3.x * e3;
            acc.y += h0.y * e0 + h1.y * e1 + h2.y * e2 + h3.y * e3;
            acc.z += h0.z * e0 + h1.z * e1 + h2.z * e2 + h3.z * e3;
            acc.w += h0.w * e0 + h1.w * e1 + h2.w * e2 + h3.w * e3;
        }
        for (; i < end; i++) {
            int s0 = g_col[i];
            float ex0 = 0.f;
            if (lane == 0) { ex0 = __expf(lrelu(g_al_s[s0 * 8] + ald)); ssum += ex0; }
            float e0 = __shfl_sync(0xffffffffu, ex0, 0);
            float4 h0 = *reinterpret_cast<const float4*>(&g_h[s0 * F + lane * 4]);
            acc.x += h0.x * e0; acc.y += h0.y * e0; acc.z += h0.z * e0; acc.w += h0.w * e0;
        }
        ssum += __shfl_xor_sync(0xffffffffu, ssum, 1);
        ssum += __shfl_xor_sync(0xffffffffu, ssum, 2);
        ssum  = __shfl_sync(0xffffffffu, ssum, 0);
    }

    float inv = 1.f / ssum;
    float4 bv = *reinterpret_cast<const float4*>(&b[lane * 4]);
    acc.x = acc.x * inv + bv.x;
    acc.y = acc.y * inv + bv.y;
    acc.z = acc.z * inv + bv.z;
    acc.w = acc.w * inv + bv.w;

    // LayerNorm across the 128 features held by this warp
    float t = acc.x + acc.y + acc.z + acc.w;
#pragma unroll
    for (int o = 1; o < 32; o <<= 1) t += __shfl_xor_sync(0xffffffffu, t, o);
    float mu = t * (1.f / F);
    float dx = acc.x - mu, dy = acc.y - mu, dz = acc.z - mu, dw = acc.w - mu;
    float v = dx * dx + dy * dy + dz * dz + dw * dw;
#pragma unroll
    for (int o = 1; o < 32; o <<= 1) v += __shfl_xor_sync(0xffffffffu, v, o);
    float rstd = rsqrtf(v * (1.f / F) + 1e-5f);

    float4 gv  = *reinterpret_cast<const float4*>(&gg[lane * 4]);
    float4 bev = *reinterpret_cast<const float4*>(&be[lane * 4]);
    float4 y;
    y.x = dx * rstd * gv.x + bev.x;
    y.y = dy * rstd * gv.y + bev.y;
    y.z = dz * rstd * gv.z + bev.z;
    y.w = dw * rstd * gv.w + bev.w;
    if (do_elu) {
        if (y.x < 0.f) y.x = __expf(y.x) - 1.f;
        if (y.y < 0.f) y.y = __expf(y.y) - 1.f;
        if (y.z < 0.f) y.z = __expf(y.z) - 1.f;
        if (y.w < 0.f) y.w = __expf(y.w) - 1.f;
    }
    float* o = out ? out : g_buf;
    *reinterpret_cast<float4*>(&o[n * F + lane * 4]) = y;
}

extern "C" void kernel_launch(void* const* d_in, const int* in_sizes, int n_in,
                              void* d_out, int out_size)
{
    const float* x  = (const float*)d_in[0];
    const int*   ei = (const int*)d_in[1];

    csr_zero<<<(Nn + 255) / 256, 256>>>();
    csr_hist<<<(ET + 255) / 256, 256>>>(ei);
    csr_scan<<<1, 1024>>>();
    csr_fill<<<(ET + 255) / 256, 256>>>(ei);

    for (int l = 0; l < 3; l++) {
        const float* W   = (const float*)d_in[2 + 6 * l];
        const float* as_ = (const float*)d_in[3 + 6 * l];
        const float* ad_ = (const float*)d_in[4 + 6 * l];
        const float* b   = (const float*)d_in[5 + 6 * l];
        const float* g   = (const float*)d_in[6 + 6 * l];
        const float* be  = (const float*)d_in[7 + 6 * l];
        int H = (l == 2) ? 1 : 8;

        gemm_attn<<<Nn / NB + (Nn % NB ? 1 : 0), 128>>>(x, l > 0 ? 1 : 0, W, as_, ad_, H);
        node_agg<<<(Nn + 7) / 8, 256>>>(b, g, be, (l == 2) ? (float*)d_out : nullptr,
                                        (l < 2) ? 1 : 0, H);
    }
}